// round 15
// baseline (speedup 1.0000x reference)
#include <cuda_runtime.h>
#include <math.h>
#include <stdint.h>

#define N_NODES 40000
#define NROWS_PAD 40064            // 313 * 128
#define E_EDGES 160000
#define G_GRAPHS 512
#define H_DIM 256
#define NHEADS 3
#define OUT_F 12
#define L_LAYERS 3
#define S2S_STEPS 6
#define HH 768

// ------------------------- scratch (device globals) -------------------------
__device__ float g_out[(size_t)NROWS_PAD * H_DIM];   // padded for 128-row tiles
__device__ float g_xn[(size_t)NROWS_PAD * HH];       // padded
__device__ float g_aggr[(size_t)NROWS_PAD * HH];     // padded
__device__ float g_ai[N_NODES * NHEADS];
__device__ float g_aj[N_NODES * NHEADS];
__device__ float g_logit[E_EDGES * NHEADS];
__device__ float g_ve[NHEADS * 16];
__device__ float g_smax[N_NODES * NHEADS];
__device__ float g_sinv[N_NODES * NHEADS];
__device__ int   g_cnt[N_NODES];
__device__ int   g_cur[N_NODES];
__device__ int   g_off[N_NODES + 1];
__device__ int   g_csr[E_EDGES];
__device__ int   g_gcnt[G_GRAPHS];
__device__ int   g_goff[G_GRAPHS + 1];
__device__ float g_A[G_GRAPHS * 768];      // [q_star | h] for gates GEMM
__device__ float g_gates[G_GRAPHS * 1024];
__device__ float g_c[G_GRAPHS * H_DIM];
__device__ float g_e[N_NODES];
__device__ float g_Wcat[768 * 1024];       // [W_ih^T ; W_hh^T]  (K-major [k][n])

// ------------------------- helpers -------------------------
__device__ __forceinline__ float warp_sum(float v) {
    #pragma unroll
    for (int o = 16; o; o >>= 1) v += __shfl_xor_sync(0xFFFFFFFFu, v, o);
    return v;
}
__device__ __forceinline__ float sigmoidf_(float x) { return 1.f / (1.f + expf(-x)); }

// ------------------------- setup kernels (proven) -------------------------
__global__ void k_zero() {
    int i = blockIdx.x * blockDim.x + threadIdx.x;
    if (i < N_NODES) { g_cnt[i] = 0; g_cur[i] = 0; }
    if (i < G_GRAPHS) g_gcnt[i] = 0;
    if (i < G_GRAPHS * 768) g_A[i] = 0.f;
    if (i < G_GRAPHS * H_DIM) g_c[i] = 0.f;
}
__global__ void k_count(const int* __restrict__ ei, const int* __restrict__ batch) {
    int i = blockIdx.x * blockDim.x + threadIdx.x;
    if (i < E_EDGES) atomicAdd(&g_cnt[ei[E_EDGES + i]], 1);
    if (i < N_NODES) atomicAdd(&g_gcnt[batch[i]], 1);
}
__device__ void scan_exclusive(const int* in, int* out, int n) {
    __shared__ int sm[1024];
    __shared__ int carry;
    int tid = threadIdx.x;
    if (tid == 0) carry = 0;
    __syncthreads();
    for (int base = 0; base < n; base += 1024) {
        int v = (base + tid < n) ? in[base + tid] : 0;
        sm[tid] = v;
        __syncthreads();
        for (int o = 1; o < 1024; o <<= 1) {
            int t = (tid >= o) ? sm[tid - o] : 0;
            __syncthreads();
            sm[tid] += t;
            __syncthreads();
        }
        int c = carry;
        if (base + tid < n) out[base + tid] = c + sm[tid] - v;
        __syncthreads();
        if (tid == 0) carry = c + sm[1023];
        __syncthreads();
    }
    if (tid == 0) out[n] = carry;
}
__global__ void k_scan_nodes()  { scan_exclusive(g_cnt,  g_off,  N_NODES);  }
__global__ void k_scan_graphs() { scan_exclusive(g_gcnt, g_goff, G_GRAPHS); }
__global__ void k_fill(const int* __restrict__ ei) {
    int e = blockIdx.x * blockDim.x + threadIdx.x;
    if (e >= E_EDGES) return;
    int d = ei[E_EDGES + e];
    int pos = atomicAdd(&g_cur[d], 1);
    g_csr[g_off[d] + pos] = e;
}
__global__ void k_sortcsr() {
    int n = blockIdx.x * blockDim.x + threadIdx.x;
    if (n >= N_NODES) return;
    int b = g_off[n], e = g_off[n + 1];
    for (int i = b + 1; i < e; i++) {
        int v = g_csr[i];
        int j = i - 1;
        while (j >= b && g_csr[j] > v) { g_csr[j + 1] = g_csr[j]; j--; }
        g_csr[j + 1] = v;
    }
}
__global__ void k_wcat(const float* __restrict__ Wih, const float* __restrict__ Whh) {
    int i = blockIdx.x * blockDim.x + threadIdx.x;
    if (i >= 768 * 1024) return;
    int k = i >> 10, t = i & 1023;
    g_Wcat[i] = (k < 512) ? Wih[t * 512 + k] : Whh[t * 256 + (k - 512)];
}

// ------------------ SIMT GEMM 64x128 (R1 + prefetch, PROVEN) ------------------
__device__ __forceinline__ void gemm_body(
    const float* __restrict__ A, const float* __restrict__ B,
    const float* __restrict__ bias, const float* Cin, float* C,
    int Nn, int K, int act)
{
    __shared__ float As[16][64];
    __shared__ float Bs[16][128];
    int tid = threadIdx.x;
    int bx = blockIdx.x, by = blockIdx.y;
    const float* Ab = A + (size_t)by * 64 * K;
    const float* Bb = B + (size_t)bx * 128;
    int a_m = tid >> 2;
    int a_k = (tid & 3) << 2;
    int b_k = tid >> 5;
    int b_c = (tid & 31) << 2;
    int ty = tid >> 4, tx = tid & 15;
    float acc[4][8];
    #pragma unroll
    for (int i = 0; i < 4; i++)
        #pragma unroll
        for (int j = 0; j < 8; j++) acc[i][j] = 0.f;

    float4 av  = *(const float4*)(Ab + (size_t)a_m * K + a_k);
    float4 bv0 = *(const float4*)(Bb + (size_t)b_k * Nn + b_c);
    float4 bv1 = *(const float4*)(Bb + (size_t)(b_k + 8) * Nn + b_c);

    for (int k0 = 0; k0 < K; k0 += 16) {
        As[a_k + 0][a_m] = av.x; As[a_k + 1][a_m] = av.y;
        As[a_k + 2][a_m] = av.z; As[a_k + 3][a_m] = av.w;
        *(float4*)&Bs[b_k][b_c]     = bv0;
        *(float4*)&Bs[b_k + 8][b_c] = bv1;
        __syncthreads();
        if (k0 + 16 < K) {
            av  = *(const float4*)(Ab + (size_t)a_m * K + (k0 + 16) + a_k);
            bv0 = *(const float4*)(Bb + (size_t)(k0 + 16 + b_k) * Nn + b_c);
            bv1 = *(const float4*)(Bb + (size_t)(k0 + 16 + b_k + 8) * Nn + b_c);
        }
        #pragma unroll
        for (int k = 0; k < 16; k++) {
            float4 a4  = *(const float4*)&As[k][ty << 2];
            float4 b4a = *(const float4*)&Bs[k][tx << 3];
            float4 b4b = *(const float4*)&Bs[k][(tx << 3) + 4];
            float ar[4] = {a4.x, a4.y, a4.z, a4.w};
            float br[8] = {b4a.x, b4a.y, b4a.z, b4a.w, b4b.x, b4b.y, b4b.z, b4b.w};
            #pragma unroll
            for (int i = 0; i < 4; i++)
                #pragma unroll
                for (int j = 0; j < 8; j++) acc[i][j] += ar[i] * br[j];
        }
        __syncthreads();
    }
    int r0 = by * 64 + (ty << 2);
    int c0 = bx * 128 + (tx << 3);
    #pragma unroll
    for (int i = 0; i < 4; i++) {
        size_t base = (size_t)(r0 + i) * Nn + c0;
        #pragma unroll
        for (int j = 0; j < 8; j++) {
            float v = acc[i][j];
            if (bias) v += bias[c0 + j];
            if (Cin)  v += Cin[base + j];
            if (act)  v = (v > 0.f) ? v : expm1f(v);
            C[base + j] = v;
        }
    }
}
__global__ void __launch_bounds__(256) k_gemm_proj(const float* x, const float* W, const float* b) {
    gemm_body(x, W, b, nullptr, g_out, 256, 64, 1);
}
__global__ void __launch_bounds__(256) k_gemm_gates() {
    gemm_body(g_A, g_Wcat, nullptr, nullptr, g_gates, 1024, 768, 0);
}

// ------- SIMT GEMM 128x128, 512 threads, SAME 4x8 microtile & index patterns -------
// A rows (by*128..+127) and C rows are within padded buffers: no bounds logic.
__device__ __forceinline__ void gemm_body512(
    const float* __restrict__ A, const float* __restrict__ B,
    const float* __restrict__ bias, const float* Cin, float* C,
    int Nn, int K)
{
    __shared__ float As[16][128];
    __shared__ float Bs[16][128];
    int tid = threadIdx.x;
    int bx = blockIdx.x, by = blockIdx.y;
    const float* Ab = A + (size_t)by * 128 * K;
    const float* Bb = B + (size_t)bx * 128;
    int a_m = tid >> 2;            // 0..127
    int a_k = (tid & 3) << 2;      // 0,4,8,12
    int b_k = tid >> 5;            // 0..15
    int b_c = (tid & 31) << 2;     // 0..124
    int ty = tid >> 4;             // 0..31 -> rows 4*ty..4*ty+3
    int tx = tid & 15;             // cols 8*tx..8*tx+7
    float acc[4][8];
    #pragma unroll
    for (int i = 0; i < 4; i++)
        #pragma unroll
        for (int j = 0; j < 8; j++) acc[i][j] = 0.f;

    float4 av  = *(const float4*)(Ab + (size_t)a_m * K + a_k);
    float4 bv0 = *(const float4*)(Bb + (size_t)b_k * Nn + b_c);

    for (int k0 = 0; k0 < K; k0 += 16) {
        As[a_k + 0][a_m] = av.x; As[a_k + 1][a_m] = av.y;
        As[a_k + 2][a_m] = av.z; As[a_k + 3][a_m] = av.w;
        *(float4*)&Bs[b_k][b_c] = bv0;
        __syncthreads();
        if (k0 + 16 < K) {
            av  = *(const float4*)(Ab + (size_t)a_m * K + (k0 + 16) + a_k);
            bv0 = *(const float4*)(Bb + (size_t)(k0 + 16 + b_k) * Nn + b_c);
        }
        #pragma unroll
        for (int k = 0; k < 16; k++) {
            float4 a4  = *(const float4*)&As[k][ty << 2];
            float4 b4a = *(const float4*)&Bs[k][tx << 3];
            float4 b4b = *(const float4*)&Bs[k][(tx << 3) + 4];
            float ar[4] = {a4.x, a4.y, a4.z, a4.w};
            float br[8] = {b4a.x, b4a.y, b4a.z, b4a.w, b4b.x, b4b.y, b4b.z, b4b.w};
            #pragma unroll
            for (int i = 0; i < 4; i++)
                #pragma unroll
                for (int j = 0; j < 8; j++) acc[i][j] += ar[i] * br[j];
        }
        __syncthreads();
    }
    int r0 = by * 128 + (ty << 2);
    int c0 = bx * 128 + (tx << 3);
    #pragma unroll
    for (int i = 0; i < 4; i++) {
        size_t base = (size_t)(r0 + i) * Nn + c0;
        #pragma unroll
        for (int j = 0; j < 8; j++) {
            float v = acc[i][j];
            if (bias) v += bias[c0 + j];
            if (Cin)  v += Cin[base + j];
            C[base + j] = v;
        }
    }
}
__global__ void __launch_bounds__(512) k_gemm_xn2(const float* W) {
    gemm_body512(g_out, W, nullptr, nullptr, g_xn, 768, 256);
}
__global__ void __launch_bounds__(512) k_gemm_res2(const float* W, const float* b) {
    gemm_body512(g_aggr, W, b, g_out, g_out, 256, 768);
}

// ------------------------- attention kernels (proven) -------------------------
__global__ void k_natt(const float* __restrict__ WattL) {
    int wid = threadIdx.x >> 5, lane = threadIdx.x & 31;
    int n = blockIdx.x * 8 + wid;
    #pragma unroll
    for (int h = 0; h < 3; h++) {
        const float* xr = g_xn + (size_t)n * HH + h * H_DIM;
        const float* wa = WattL + h * HH;
        float si = 0.f, sj = 0.f;
        for (int d = lane; d < H_DIM; d += 32) {
            float v = xr[d];
            si += v * wa[d];
            sj += v * wa[512 + d];
        }
        si = warp_sum(si); sj = warp_sum(sj);
        if (lane == 0) { g_ai[n * 3 + h] = si; g_aj[n * 3 + h] = sj; }
    }
}
__global__ void k_ve(const float* __restrict__ WeL, const float* __restrict__ WattL) {
    int t = threadIdx.x;
    if (t < 48) {
        int h = t / 16, k = t % 16;
        const float* w  = WeL + k * HH + h * H_DIM;
        const float* wa = WattL + h * HH + H_DIM;
        float s = 0.f;
        for (int d = 0; d < H_DIM; d++) s += w[d] * wa[d];
        g_ve[h * 16 + k] = s;
    }
}
__global__ void k_elogit(const int* __restrict__ ei, const float* __restrict__ eattr) {
    int e = blockIdx.x * blockDim.x + threadIdx.x;
    if (e >= E_EDGES) return;
    int s = ei[e], d = ei[E_EDGES + e];
    const float4* ep = (const float4*)(eattr + (size_t)e * 16);
    float4 v0 = ep[0], v1 = ep[1], v2 = ep[2], v3 = ep[3];
    float a[16] = {v0.x, v0.y, v0.z, v0.w, v1.x, v1.y, v1.z, v1.w,
                   v2.x, v2.y, v2.z, v2.w, v3.x, v3.y, v3.z, v3.w};
    #pragma unroll
    for (int h = 0; h < 3; h++) {
        float ae = 0.f;
        #pragma unroll
        for (int k = 0; k < 16; k++) ae += a[k] * g_ve[h * 16 + k];
        float lg = g_ai[d * 3 + h] + ae + g_aj[s * 3 + h];
        g_logit[e * 3 + h] = (lg > 0.f) ? lg : 0.2f * lg;
    }
}
__global__ void k_segsoft() {
    int i = blockIdx.x * blockDim.x + threadIdx.x;
    if (i >= N_NODES * 3) return;
    int n = i / 3, h = i - 3 * n;
    int b = g_off[n], e = g_off[n + 1];
    float m = -INFINITY;
    for (int j = b; j < e; j++) m = fmaxf(m, g_logit[g_csr[j] * 3 + h]);
    float s = 0.f;
    for (int j = b; j < e; j++) s += __expf(g_logit[g_csr[j] * 3 + h] - m);
    g_smax[i] = m;
    g_sinv[i] = 1.f / (s + 1e-16f);
}

// ---------------- fused aggregation (proven; softmax weights inline) ----------------
__global__ void __launch_bounds__(256) k_aggr3(const int* __restrict__ ei,
                                               const float* __restrict__ eattr,
                                               const float* __restrict__ WeL) {
    int tid = threadIdx.x;
    float rwe0[16], rwe1[16], rwe2[16];
    #pragma unroll
    for (int k = 0; k < 16; k++) {
        rwe0[k] = WeL[k * 768 + tid];
        rwe1[k] = WeL[k * 768 + 256 + tid];
        rwe2[k] = WeL[k * 768 + 512 + tid];
    }
    __shared__ float sea[16][16];
    __shared__ float sw[16][3];
    __shared__ int ssrc[16];
    __shared__ int sedge[16];
    int nb = blockIdx.x * 4;
    for (int n = nb; n < nb + 4; n++) {
        int b = g_off[n], e = g_off[n + 1];
        float a0 = 0.f, a1 = 0.f, a2 = 0.f;
        for (int c0 = b; c0 < e; c0 += 16) {
            int cn = min(16, e - c0);
            if (tid < cn) sedge[tid] = g_csr[c0 + tid];
            __syncthreads();
            if (tid < cn * 16) {
                int i = tid >> 4, k = tid & 15;
                sea[i][k] = eattr[(size_t)sedge[i] * 16 + k];
            }
            if (tid < cn) {
                int ed = sedge[tid];
                ssrc[tid] = ei[ed];
                #pragma unroll
                for (int h = 0; h < 3; h++)
                    sw[tid][h] = __expf(g_logit[ed * 3 + h] - g_smax[n * 3 + h])
                               * g_sinv[n * 3 + h];
            }
            __syncthreads();
            for (int i = 0; i < cn; i++) {
                float e0 = 0.f, e1 = 0.f, e2 = 0.f;
                #pragma unroll
                for (int k = 0; k < 16; k++) {
                    float a = sea[i][k];
                    e0 += a * rwe0[k];
                    e1 += a * rwe1[k];
                    e2 += a * rwe2[k];
                }
                size_t sb = (size_t)ssrc[i] * 768;
                a0 += sw[i][0] * e0 * g_xn[sb + tid];
                a1 += sw[i][1] * e1 * g_xn[sb + 256 + tid];
                a2 += sw[i][2] * e2 * g_xn[sb + 512 + tid];
            }
            __syncthreads();
        }
        size_t nbase = (size_t)n * 768;
        g_aggr[nbase + tid] = a0;
        g_aggr[nbase + 256 + tid] = a1;
        g_aggr[nbase + 512 + tid] = a2;
    }
}

// ------------------------- Set2Set (proven) -------------------------
__global__ void k_attend(const float* __restrict__ bih, const float* __restrict__ bhh) {
    int g = blockIdx.x, tid = threadIdx.x;
    __shared__ float sh[256];
    __shared__ float red[8];
    __shared__ float s_gmax, s_inv;
    {
        const float* gr = g_gates + g * 1024;
        float gi = gr[tid]       + bih[tid]       + bhh[tid];
        float gf = gr[256 + tid] + bih[256 + tid] + bhh[256 + tid];
        float gg = gr[512 + tid] + bih[512 + tid] + bhh[512 + tid];
        float go = gr[768 + tid] + bih[768 + tid] + bhh[768 + tid];
        float c = sigmoidf_(gf) * g_c[g * 256 + tid] + sigmoidf_(gi) * tanhf(gg);
        g_c[g * 256 + tid] = c;
        sh[tid] = sigmoidf_(go) * tanhf(c);
    }
    __syncthreads();
    int b = g_goff[g], e = g_goff[g + 1];
    int wid = tid >> 5, lane = tid & 31;
    float wmax = -INFINITY;
    for (int n = b + wid; n < e; n += 8) {
        const float* orow = g_out + (size_t)n * 256;
        float p = 0.f;
        for (int d = lane; d < 256; d += 32) p += orow[d] * sh[d];
        p = warp_sum(p);
        if (lane == 0) g_e[n] = p;
        wmax = fmaxf(wmax, p);
    }
    if (lane == 0) red[wid] = wmax;
    __syncthreads();
    if (tid == 0) {
        float m = red[0];
        for (int i = 1; i < 8; i++) m = fmaxf(m, red[i]);
        s_gmax = m;
    }
    __syncthreads();
    float gmax = s_gmax;
    float ps = 0.f;
    for (int n = b + tid; n < e; n += 256) ps += __expf(g_e[n] - gmax);
    ps = warp_sum(ps);
    __syncthreads();
    if (lane == 0) red[wid] = ps;
    __syncthreads();
    if (tid == 0) {
        float s = 0.f;
        for (int i = 0; i < 8; i++) s += red[i];
        s_inv = 1.f / (s + 1e-16f);
    }
    __syncthreads();
    float inv = s_inv;
    __shared__ float swt[128];
    float r = 0.f;
    for (int c0 = b; c0 < e; c0 += 128) {
        int cn = min(128, e - c0);
        if (tid < cn) swt[tid] = __expf(g_e[c0 + tid] - gmax) * inv;
        __syncthreads();
        for (int i = 0; i < cn; i++) r += swt[i] * g_out[(size_t)(c0 + i) * 256 + tid];
        __syncthreads();
    }
    float h = sh[tid];
    g_A[g * 768 + tid] = h;
    g_A[g * 768 + 256 + tid] = r;
    g_A[g * 768 + 512 + tid] = h;
}

// ------------------------- MLP head (proven) -------------------------
__global__ void k_head(const float* __restrict__ W1, const float* __restrict__ b1,
                       const float* __restrict__ lg, const float* __restrict__ lb,
                       const float* __restrict__ W2, const float* __restrict__ b2,
                       float* __restrict__ outp) {
    int g = blockIdx.x, tid = threadIdx.x;
    __shared__ float sq[512];
    __shared__ float red[8];
    __shared__ float s_mu, s_rstd;
    __shared__ float sy[256];
    sq[tid]       = g_A[g * 768 + tid];
    sq[256 + tid] = g_A[g * 768 + 256 + tid];
    __syncthreads();
    float y = b1[tid];
    for (int k = 0; k < 512; k++) y += sq[k] * W1[k * 256 + tid];
    int wid = tid >> 5, lane = tid & 31;
    float s1 = warp_sum(y);
    if (lane == 0) red[wid] = s1;
    __syncthreads();
    if (tid == 0) {
        float s = 0.f;
        for (int i = 0; i < 8; i++) s += red[i];
        s_mu = s * (1.f / 256.f);
    }
    __syncthreads();
    float mu = s_mu;
    float dv = y - mu;
    float s2 = warp_sum(dv * dv);
    __syncthreads();
    if (lane == 0) red[wid] = s2;
    __syncthreads();
    if (tid == 0) {
        float s = 0.f;
        for (int i = 0; i < 8; i++) s += red[i];
        s_rstd = rsqrtf(s * (1.f / 256.f) + 1e-5f);
    }
    __syncthreads();
    float yn = dv * s_rstd * lg[tid] + lb[tid];
    yn = fmaxf(yn, 0.f);
    sy[tid] = yn;
    __syncthreads();
    if (tid < 12) {
        float s = b2[tid];
        for (int t = 0; t < 256; t++) s += sy[t] * W2[t * 12 + tid];
        outp[g * 12 + tid] = s;
    }
}

// ------------------------- launch -------------------------
extern "C" void kernel_launch(void* const* d_in, const int* in_sizes, int n_in,
                              void* d_out, int out_size) {
    const float* x     = (const float*)d_in[0];
    const float* eattr = (const float*)d_in[1];
    const int*   eidx  = (const int*)  d_in[2];
    const int*   batch = (const int*)  d_in[3];
    const float* projW = (const float*)d_in[4];
    const float* projb = (const float*)d_in[5];
    const float* Wn    = (const float*)d_in[6];
    const float* We    = (const float*)d_in[7];
    const float* Watt  = (const float*)d_in[8];
    const float* Ws    = (const float*)d_in[9];
    const float* bl    = (const float*)d_in[10];
    const float* Wih   = (const float*)d_in[11];
    const float* Whh   = (const float*)d_in[12];
    const float* bih   = (const float*)d_in[13];
    const float* bhh   = (const float*)d_in[14];
    const float* W1    = (const float*)d_in[15];
    const float* b1    = (const float*)d_in[16];
    const float* lng   = (const float*)d_in[17];
    const float* lnb   = (const float*)d_in[18];
    const float* W2    = (const float*)d_in[19];
    const float* b2    = (const float*)d_in[20];
    float* outp = (float*)d_out;

    const int MT128 = NROWS_PAD / 128;   // 313

    // Launch order arranged so launch #4 (the ncu-profiled slot) is the xn GEMM.
    k_zero<<<(G_GRAPHS * 768 + 255) / 256, 256>>>();                        // 1
    k_count<<<(E_EDGES + 255) / 256, 256>>>(eidx, batch);                   // 2
    k_gemm_proj<<<dim3(2, N_NODES / 64), 256>>>(x, projW, projb);           // 3
    k_gemm_xn2<<<dim3(6, MT128), 512>>>(Wn);                                // 4 (layer 0)
    k_scan_nodes<<<1, 1024>>>();                                            // 5
    k_scan_graphs<<<1, 1024>>>();
    k_fill<<<(E_EDGES + 255) / 256, 256>>>(eidx);
    k_sortcsr<<<(N_NODES + 255) / 256, 256>>>();
    k_wcat<<<(768 * 1024 + 255) / 256, 256>>>(Wih, Whh);

    for (int l = 0; l < L_LAYERS; l++) {
        const float* WnL   = Wn   + (size_t)l * 256 * 768;
        const float* WeL   = We   + (size_t)l * 16 * 768;
        const float* WattL = Watt + (size_t)l * 3 * 768;
        const float* WsL   = Ws   + (size_t)l * 768 * 256;
        const float* blL   = bl   + (size_t)l * 256;
        if (l > 0) k_gemm_xn2<<<dim3(6, MT128), 512>>>(WnL);  // layer 0 already done
        k_natt<<<N_NODES / 8, 256>>>(WattL);
        k_ve<<<1, 64>>>(WeL, WattL);
        k_elogit<<<(E_EDGES + 255) / 256, 256>>>(eidx, eattr);
        k_segsoft<<<(N_NODES * 3 + 255) / 256, 256>>>();
        k_aggr3<<<N_NODES / 4, 256>>>(eidx, eattr, WeL);
        k_gemm_res2<<<dim3(2, MT128), 512>>>(WsL, blL);
    }

    // Set2Set
    for (int s = 0; s < S2S_STEPS; s++) {
        k_gemm_gates<<<dim3(8, G_GRAPHS / 64), 256>>>();
        k_attend<<<G_GRAPHS, 256>>>(bih, bhh);
    }

    k_head<<<G_GRAPHS, 256>>>(W1, b1, lng, lnb, W2, b2, outp);
}